// round 2
// baseline (speedup 1.0000x reference)
#include <cuda_runtime.h>
#include <math.h>

#define DDIM 128
#define NMAX 50000
#define EMAX 800000

// Scratch (alloc-free rule: __device__ globals)
__device__ float g_support[(size_t)NMAX * DDIM];
__device__ float g_agg[(size_t)NMAX * DDIM];

// ---------------------------------------------------------------------------
// Zero the aggregation buffer (float4 stores)
// ---------------------------------------------------------------------------
__global__ void zero_agg_kernel(int total4) {
    int i = blockIdx.x * blockDim.x + threadIdx.x;
    if (i < total4) ((float4*)g_agg)[i] = make_float4(0.f, 0.f, 0.f, 0.f);
}

// ---------------------------------------------------------------------------
// TF32 split: v = hi + lo, both rounded to tf32. Error ~2^-23 relative.
// ---------------------------------------------------------------------------
__device__ __forceinline__ void split_tf32(float v, float& hi, float& lo) {
    unsigned h;
    asm("cvt.rna.tf32.f32 %0, %1;" : "=r"(h) : "f"(v));
    float hf = __uint_as_float(h);
    float l = v - hf;                 // exact (<=13 significant bits)
    unsigned lw;
    asm("cvt.rna.tf32.f32 %0, %1;" : "=r"(lw) : "f"(l));
    hi = hf;
    lo = __uint_as_float(lw);
}

__device__ __forceinline__ void mma_tf32(float c[4],
                                         unsigned a0, unsigned a1, unsigned a2, unsigned a3,
                                         unsigned b0, unsigned b1) {
    asm volatile(
        "mma.sync.aligned.m16n8k8.row.col.f32.tf32.tf32.f32 "
        "{%0,%1,%2,%3}, {%4,%5,%6,%7}, {%8,%9}, {%0,%1,%2,%3};"
        : "+f"(c[0]), "+f"(c[1]), "+f"(c[2]), "+f"(c[3])
        : "r"(a0), "r"(a1), "r"(a2), "r"(a3), "r"(b0), "r"(b1));
}

// ---------------------------------------------------------------------------
// Tensor-core GEMM, 3xTF32 split for fp32-grade accuracy.
// Block: 128 rows x 128 cols, 8 warps; each warp owns 16 full-width rows
// (so the MODE-1 row-norm reduction is a 4-lane shfl, no cross-warp step).
// MODE 0: out = X @ W + b              (Bs layout [k][n], stride 136, direct copy)
// MODE 1: out = rownorm(relu(X) @ W^T + b)  (Bs layout [n][k], stride 36, direct copy)
// All fragment LDS patterns are bank-conflict-free (strides 36 / 136).
// ---------------------------------------------------------------------------
#define ASTR 36
#define BKNSTR 136

template <int MODE>
__global__ void __launch_bounds__(256)
mma_gemm_kernel(const float* __restrict__ X,
                const float* __restrict__ W,
                const float* __restrict__ bias,
                float* __restrict__ out, int n) {
    extern __shared__ float sm[];
    float* Ahi = sm;                         // [128][36]
    float* Alo = sm + 128 * ASTR;
    float* Bhi = sm + 2 * 128 * ASTR;        // MODE0: [32][136]; MODE1: [128][36]
    float* Blo = Bhi + (MODE == 0 ? 32 * BKNSTR : 128 * ASTR);

    const int tid  = threadIdx.x;
    const int lane = tid & 31;
    const int wid  = tid >> 5;
    const int g    = lane >> 2;   // 0..7
    const int t4   = lane & 3;    // 0..3
    const int rb   = blockIdx.x * 128;

    float acc[16][4];
#pragma unroll
    for (int t = 0; t < 16; t++)
#pragma unroll
        for (int j = 0; j < 4; j++) acc[t][j] = 0.f;

    for (int kc0 = 0; kc0 < DDIM; kc0 += 32) {
        // ---- stage A chunk [128 rows][32 k], split hi/lo ----
        {
            int rl  = tid >> 3;            // 0..31
            int col = (tid & 7) * 4;       // 0..28
#pragma unroll
            for (int i = 0; i < 4; i++) {
                int row  = rl + 32 * i;
                int grow = rb + row;
                float4 v = make_float4(0.f, 0.f, 0.f, 0.f);
                if (grow < n)
                    v = *(const float4*)(X + (size_t)grow * DDIM + kc0 + col);
                if (MODE == 1) {
                    v.x = fmaxf(v.x, 0.f); v.y = fmaxf(v.y, 0.f);
                    v.z = fmaxf(v.z, 0.f); v.w = fmaxf(v.w, 0.f);
                }
                float* ph = Ahi + row * ASTR + col;
                float* pl = Alo + row * ASTR + col;
                split_tf32(v.x, ph[0], pl[0]);
                split_tf32(v.y, ph[1], pl[1]);
                split_tf32(v.z, ph[2], pl[2]);
                split_tf32(v.w, ph[3], pl[3]);
            }
        }
        // ---- stage B chunk, split hi/lo (no transpose needed either mode) ----
        if (MODE == 0) {
            // Bs[k][n] = W[kc0+k][n], k in 0..31, stride 136
            int kl = tid >> 3;             // 0..31
            int nb = (tid & 7) * 16;       // 0..112
#pragma unroll
            for (int i = 0; i < 4; i++) {
                int nn = nb + 4 * i;
                float4 v = *(const float4*)(W + (size_t)(kc0 + kl) * DDIM + nn);
                float* ph = Bhi + kl * BKNSTR + nn;
                float* pl = Blo + kl * BKNSTR + nn;
                split_tf32(v.x, ph[0], pl[0]);
                split_tf32(v.y, ph[1], pl[1]);
                split_tf32(v.z, ph[2], pl[2]);
                split_tf32(v.w, ph[3], pl[3]);
            }
        } else {
            // Bs[n][k] = W2[n][kc0+k], stride 36
            int nl  = tid >> 3;
            int col = (tid & 7) * 4;
#pragma unroll
            for (int i = 0; i < 4; i++) {
                int nn = nl + 32 * i;
                float4 v = *(const float4*)(W + (size_t)nn * DDIM + kc0 + col);
                float* ph = Bhi + nn * ASTR + col;
                float* pl = Blo + nn * ASTR + col;
                split_tf32(v.x, ph[0], pl[0]);
                split_tf32(v.y, ph[1], pl[1]);
                split_tf32(v.z, ph[2], pl[2]);
                split_tf32(v.w, ph[3], pl[3]);
            }
        }
        __syncthreads();

        // ---- compute: 4 k-steps of 8 ----
#pragma unroll
        for (int ks = 0; ks < 4; ks++) {
            int kb = ks * 8;
            const float* Ar = Ahi + (wid * 16 + g) * ASTR + kb + t4;
            const float* Al = Alo + (wid * 16 + g) * ASTR + kb + t4;
            unsigned ah0 = __float_as_uint(Ar[0]);
            unsigned ah1 = __float_as_uint(Ar[8 * ASTR]);
            unsigned ah2 = __float_as_uint(Ar[4]);
            unsigned ah3 = __float_as_uint(Ar[8 * ASTR + 4]);
            unsigned al0 = __float_as_uint(Al[0]);
            unsigned al1 = __float_as_uint(Al[8 * ASTR]);
            unsigned al2 = __float_as_uint(Al[4]);
            unsigned al3 = __float_as_uint(Al[8 * ASTR + 4]);
#pragma unroll
            for (int t = 0; t < 16; t++) {
                int nb = t * 8 + g;
                unsigned bh0, bh1, bl0, bl1;
                if (MODE == 0) {
                    bh0 = __float_as_uint(Bhi[(kb + t4) * BKNSTR + nb]);
                    bh1 = __float_as_uint(Bhi[(kb + t4 + 4) * BKNSTR + nb]);
                    bl0 = __float_as_uint(Blo[(kb + t4) * BKNSTR + nb]);
                    bl1 = __float_as_uint(Blo[(kb + t4 + 4) * BKNSTR + nb]);
                } else {
                    bh0 = __float_as_uint(Bhi[nb * ASTR + kb + t4]);
                    bh1 = __float_as_uint(Bhi[nb * ASTR + kb + t4 + 4]);
                    bl0 = __float_as_uint(Blo[nb * ASTR + kb + t4]);
                    bl1 = __float_as_uint(Blo[nb * ASTR + kb + t4 + 4]);
                }
                mma_tf32(acc[t], ah0, ah1, ah2, ah3, bh0, bh1);
                mma_tf32(acc[t], ah0, ah1, ah2, ah3, bl0, bl1);
                mma_tf32(acc[t], al0, al1, al2, al3, bh0, bh1);
            }
        }
        __syncthreads();
    }

    // ---- epilogue ----
    const int row0 = rb + wid * 16 + g;
    const int row1 = row0 + 8;

    if (MODE == 0) {
#pragma unroll
        for (int t = 0; t < 16; t++) {
            int col = t * 8 + 2 * t4;
            float b0 = __ldg(bias + col), b1 = __ldg(bias + col + 1);
            if (row0 < n) {
                float2 v = make_float2(acc[t][0] + b0, acc[t][1] + b1);
                *(float2*)(out + (size_t)row0 * DDIM + col) = v;
            }
            if (row1 < n) {
                float2 v = make_float2(acc[t][2] + b0, acc[t][3] + b1);
                *(float2*)(out + (size_t)row1 * DDIM + col) = v;
            }
        }
    } else {
        float ss0 = 0.f, ss1 = 0.f;
#pragma unroll
        for (int t = 0; t < 16; t++) {
            int col = t * 8 + 2 * t4;
            float b0 = __ldg(bias + col), b1 = __ldg(bias + col + 1);
            acc[t][0] += b0; acc[t][1] += b1;
            acc[t][2] += b0; acc[t][3] += b1;
            ss0 = fmaf(acc[t][0], acc[t][0], ss0);
            ss0 = fmaf(acc[t][1], acc[t][1], ss0);
            ss1 = fmaf(acc[t][2], acc[t][2], ss1);
            ss1 = fmaf(acc[t][3], acc[t][3], ss1);
        }
        // reduce across the 4 lanes sharing each row (t4 = bits 0..1)
        ss0 += __shfl_xor_sync(0xffffffffu, ss0, 1);
        ss0 += __shfl_xor_sync(0xffffffffu, ss0, 2);
        ss1 += __shfl_xor_sync(0xffffffffu, ss1, 1);
        ss1 += __shfl_xor_sync(0xffffffffu, ss1, 2);
        float i0 = 1.f / sqrtf(ss0);
        float i1 = 1.f / sqrtf(ss1);
#pragma unroll
        for (int t = 0; t < 16; t++) {
            int col = t * 8 + 2 * t4;
            if (row0 < n) {
                float2 v = make_float2(acc[t][0] * i0, acc[t][1] * i0);
                *(float2*)(out + (size_t)row0 * DDIM + col) = v;
            }
            if (row1 < n) {
                float2 v = make_float2(acc[t][2] * i1, acc[t][3] * i1);
                *(float2*)(out + (size_t)row1 * DDIM + col) = v;
            }
        }
    }
}

// ---------------------------------------------------------------------------
// Edge scatter: one warp per edge. Gather support[src] (float4/lane), scale by
// vals[e], vector reduce-add into agg[dst]. Both buffers are L2-resident.
// ---------------------------------------------------------------------------
__global__ void scatter_kernel(const int* __restrict__ src,
                               const int* __restrict__ dst,
                               const float* __restrict__ vals, int e) {
    int g = blockIdx.x * blockDim.x + threadIdx.x;
    int edge = g >> 5;
    int lane = g & 31;
    if (edge >= e) return;
    int s = __ldg(src + edge);
    int d = __ldg(dst + edge);
    float v = __ldg(vals + edge);
    float4 m = ((const float4*)(g_support + (size_t)s * DDIM))[lane];
    m.x *= v; m.y *= v; m.z *= v; m.w *= v;
    float* a = g_agg + (size_t)d * DDIM + lane * 4;
    asm volatile("red.global.add.v4.f32 [%0], {%1, %2, %3, %4};"
                 :: "l"(a), "f"(m.x), "f"(m.y), "f"(m.z), "f"(m.w)
                 : "memory");
}

// ---------------------------------------------------------------------------
extern "C" void kernel_launch(void* const* d_in, const int* in_sizes, int n_in,
                              void* d_out, int out_size) {
    const float* x    = (const float*)d_in[0];
    const float* vals = (const float*)d_in[1];
    const float* W_gc = (const float*)d_in[2];
    const float* b_gc = (const float*)d_in[3];
    const float* W2   = (const float*)d_in[4];
    const float* b2   = (const float*)d_in[5];
    const int*   src  = (const int*)d_in[6];
    const int*   dst  = (const int*)d_in[7];

    const int n = in_sizes[0] / DDIM;
    const int e = in_sizes[1];

    float *support, *agg;
    cudaGetSymbolAddress((void**)&support, g_support);
    cudaGetSymbolAddress((void**)&agg, g_agg);

    const int smem0 = (2 * 128 * ASTR + 2 * 32 * BKNSTR) * 4;  // 71680
    const int smem1 = (2 * 128 * ASTR + 2 * 128 * ASTR) * 4;   // 73728
    cudaFuncSetAttribute(mma_gemm_kernel<0>,
                         cudaFuncAttributeMaxDynamicSharedMemorySize, smem0);
    cudaFuncSetAttribute(mma_gemm_kernel<1>,
                         cudaFuncAttributeMaxDynamicSharedMemorySize, smem1);

    // 1) zero agg  2) support = x @ W_gc + b_gc
    int total4 = n * (DDIM / 4);
    zero_agg_kernel<<<(total4 + 255) / 256, 256>>>(total4);

    int gblocks = (n + 127) / 128;
    mma_gemm_kernel<0><<<gblocks, 256, smem0>>>(x, W_gc, b_gc, support, n);

    // 3) agg[dst] += support[src] * vals  (one warp per edge)
    long long sthreads = (long long)e * 32;
    scatter_kernel<<<(int)((sthreads + 255) / 256), 256>>>(src, dst, vals, e);

    // 4) out = rownorm(relu(agg) @ W2^T + b2)
    mma_gemm_kernel<1><<<gblocks, 256, smem1>>>(agg, W2, b2, (float*)d_out, n);
}

// round 3
// speedup vs baseline: 1.6641x; 1.6641x over previous
#include <cuda_runtime.h>
#include <cuda_bf16.h>
#include <math.h>

#define DDIM 128
#define NMAX 50000
#define EMAX 800000
#define ASTR 36            // bf16x2 stride per row (32 data + 4 pad), 36%32==4 -> conflict-free frags
#define KC   64            // k-chunk (32 bf16x2)

// Scratch (alloc-free rule: __device__ globals)
__device__ float g_support[(size_t)NMAX * DDIM];
__device__ float g_agg[(size_t)NMAX * DDIM];

// ---------------------------------------------------------------------------
__global__ void zero_agg_kernel(int total4) {
    int i = blockIdx.x * blockDim.x + threadIdx.x;
    if (i < total4) ((float4*)g_agg)[i] = make_float4(0.f, 0.f, 0.f, 0.f);
}

// ---------------------------------------------------------------------------
// bf16 split: v = hi + lo (both bf16). Residual ~2^-18 relative.
// pack2: (even_k, odd_k) -> bf16x2 register (even in low half).
// ---------------------------------------------------------------------------
__device__ __forceinline__ void split_pair(float x, float y, unsigned& hp, unsigned& lp) {
    __nv_bfloat16 hx = __float2bfloat16_rn(x);
    __nv_bfloat16 hy = __float2bfloat16_rn(y);
    __nv_bfloat16 lx = __float2bfloat16_rn(x - __bfloat162float(hx));
    __nv_bfloat16 ly = __float2bfloat16_rn(y - __bfloat162float(hy));
    hp = (unsigned)__bfloat16_as_ushort(hx) | ((unsigned)__bfloat16_as_ushort(hy) << 16);
    lp = (unsigned)__bfloat16_as_ushort(lx) | ((unsigned)__bfloat16_as_ushort(ly) << 16);
}

__device__ __forceinline__ void mma_bf16(float c[4], const unsigned a[4],
                                         unsigned b0, unsigned b1) {
    asm volatile(
        "mma.sync.aligned.m16n8k16.row.col.f32.bf16.bf16.f32 "
        "{%0,%1,%2,%3}, {%4,%5,%6,%7}, {%8,%9}, {%0,%1,%2,%3};"
        : "+f"(c[0]), "+f"(c[1]), "+f"(c[2]), "+f"(c[3])
        : "r"(a[0]), "r"(a[1]), "r"(a[2]), "r"(a[3]), "r"(b0), "r"(b1));
}

// ---------------------------------------------------------------------------
// bf16 3-split tensor-core GEMM. Block 128x128, 8 warps in 4(M) x 2(N) grid,
// warp tile 32x64. 2 k-chunks of 64. All fragment LDS conflict-free.
// MODE 0: out = X @ W + b                  (B staging transposes W -> [n][k])
// MODE 1: out = rownorm(relu(X) @ W2^T + b) (W2 is [n][k] already, direct copy)
// ---------------------------------------------------------------------------
template <int MODE>
__global__ void __launch_bounds__(256, 2)
hgemm_kernel(const float* __restrict__ X,
             const float* __restrict__ W,
             const float* __restrict__ bias,
             float* __restrict__ out, int n) {
    extern __shared__ unsigned smu[];
    unsigned* Ah = smu;                  // [128][36] bf16x2
    unsigned* Al = smu + 128 * ASTR;
    unsigned* Bh = smu + 2 * 128 * ASTR;
    unsigned* Bl = smu + 3 * 128 * ASTR;

    const int tid  = threadIdx.x;
    const int lane = tid & 31;
    const int wid  = tid >> 5;
    const int gid  = lane >> 2;      // 0..7
    const int tg   = lane & 3;       // 0..3
    const int wm   = wid >> 1;       // 0..3  (M)
    const int wn   = wid & 1;        // 0..1  (N)
    const int rb   = blockIdx.x * 128;

    float acc[2][8][4];
#pragma unroll
    for (int mt = 0; mt < 2; mt++)
#pragma unroll
        for (int nt = 0; nt < 8; nt++)
#pragma unroll
            for (int j = 0; j < 4; j++) acc[mt][nt][j] = 0.f;

#pragma unroll
    for (int kc0 = 0; kc0 < DDIM; kc0 += KC) {
        // ---- stage A [128][64], split hi/lo ----
        {
            int rl = tid >> 4;            // 0..15
            int c4 = (tid & 15) * 4;      // 0..60
#pragma unroll
            for (int i = 0; i < 8; i++) {
                int row  = rl + 16 * i;
                int grow = rb + row;
                float4 v = make_float4(0.f, 0.f, 0.f, 0.f);
                if (grow < n)
                    v = *(const float4*)(X + (size_t)grow * DDIM + kc0 + c4);
                if (MODE == 1) {
                    v.x = fmaxf(v.x, 0.f); v.y = fmaxf(v.y, 0.f);
                    v.z = fmaxf(v.z, 0.f); v.w = fmaxf(v.w, 0.f);
                }
                unsigned h0, l0, h1, l1;
                split_pair(v.x, v.y, h0, l0);
                split_pair(v.z, v.w, h1, l1);
                int sa = row * ASTR + (c4 >> 1);
                *(uint2*)(Ah + sa) = make_uint2(h0, h1);
                *(uint2*)(Al + sa) = make_uint2(l0, l1);
            }
        }
        // ---- stage B [128 n][64 k] ----
        if (MODE == 1) {
            // W2 row-major [n][k]: direct copy
            int rl = tid >> 4;
            int c4 = (tid & 15) * 4;
#pragma unroll
            for (int i = 0; i < 8; i++) {
                int nr = rl + 16 * i;
                float4 v = *(const float4*)(W + (size_t)nr * DDIM + kc0 + c4);
                unsigned h0, l0, h1, l1;
                split_pair(v.x, v.y, h0, l0);
                split_pair(v.z, v.w, h1, l1);
                int sa = nr * ASTR + (c4 >> 1);
                *(uint2*)(Bh + sa) = make_uint2(h0, h1);
                *(uint2*)(Bl + sa) = make_uint2(l0, l1);
            }
        } else {
            // W row-major [k][n]: transpose into [n][k]
            int nn0 = tid & 31;
            int kh  = tid >> 5;          // 0..7
#pragma unroll
            for (int ik = 0; ik < 4; ik++) {
                int k2l = kh + 8 * ik;   // 0..31 (bf16x2 index in chunk)
                int gk  = kc0 + 2 * k2l;
#pragma unroll
                for (int jn = 0; jn < 4; jn++) {
                    int nn = nn0 + 32 * jn;
                    float w0 = __ldg(W + (size_t)gk * DDIM + nn);
                    float w1 = __ldg(W + (size_t)(gk + 1) * DDIM + nn);
                    unsigned hp, lp;
                    split_pair(w0, w1, hp, lp);
                    Bh[nn * ASTR + k2l] = hp;
                    Bl[nn * ASTR + k2l] = lp;
                }
            }
        }
        __syncthreads();

        // ---- compute: 4 k16-steps ----
#pragma unroll
        for (int ks = 0; ks < 4; ks++) {
            int kb = ks * 8;
            unsigned ah[2][4], al[2][4];
#pragma unroll
            for (int mt = 0; mt < 2; mt++) {
                int base = (wm * 32 + mt * 16 + gid) * ASTR + kb + tg;
                ah[mt][0] = Ah[base];
                ah[mt][1] = Ah[base + 8 * ASTR];
                ah[mt][2] = Ah[base + 4];
                ah[mt][3] = Ah[base + 8 * ASTR + 4];
                al[mt][0] = Al[base];
                al[mt][1] = Al[base + 8 * ASTR];
                al[mt][2] = Al[base + 4];
                al[mt][3] = Al[base + 8 * ASTR + 4];
            }
#pragma unroll
            for (int nt = 0; nt < 8; nt++) {
                int nb = (wn * 64 + nt * 8 + gid) * ASTR + kb + tg;
                unsigned bh0 = Bh[nb], bh1 = Bh[nb + 4];
                unsigned bl0 = Bl[nb], bl1 = Bl[nb + 4];
#pragma unroll
                for (int mt = 0; mt < 2; mt++) {
                    mma_bf16(acc[mt][nt], ah[mt], bh0, bh1);
                    mma_bf16(acc[mt][nt], ah[mt], bl0, bl1);
                    mma_bf16(acc[mt][nt], al[mt], bh0, bh1);
                }
            }
        }
        __syncthreads();
    }

    // ---- epilogue ----
    if (MODE == 0) {
#pragma unroll
        for (int mt = 0; mt < 2; mt++)
#pragma unroll
            for (int h = 0; h < 2; h++) {
                int row = rb + wm * 32 + mt * 16 + h * 8 + gid;
                if (row < n) {
#pragma unroll
                    for (int nt = 0; nt < 8; nt++) {
                        int col = wn * 64 + nt * 8 + tg * 2;
                        float b0 = __ldg(bias + col), b1 = __ldg(bias + col + 1);
                        float2 v = make_float2(acc[mt][nt][2 * h] + b0,
                                               acc[mt][nt][2 * h + 1] + b1);
                        *(float2*)(out + (size_t)row * DDIM + col) = v;
                    }
                }
            }
    } else {
        // add bias, per-row sum-of-squares, cross-warp (2 N-warps) reduce
        float* red = (float*)smu;        // [128][2], safe after trailing sync
#pragma unroll
        for (int mt = 0; mt < 2; mt++)
#pragma unroll
            for (int nt = 0; nt < 8; nt++) {
                int col = wn * 64 + nt * 8 + tg * 2;
                float b0 = __ldg(bias + col), b1 = __ldg(bias + col + 1);
                acc[mt][nt][0] += b0; acc[mt][nt][1] += b1;
                acc[mt][nt][2] += b0; acc[mt][nt][3] += b1;
            }
#pragma unroll
        for (int mt = 0; mt < 2; mt++)
#pragma unroll
            for (int h = 0; h < 2; h++) {
                float ss = 0.f;
#pragma unroll
                for (int nt = 0; nt < 8; nt++) {
                    ss = fmaf(acc[mt][nt][2 * h], acc[mt][nt][2 * h], ss);
                    ss = fmaf(acc[mt][nt][2 * h + 1], acc[mt][nt][2 * h + 1], ss);
                }
                ss += __shfl_xor_sync(0xffffffffu, ss, 1);
                ss += __shfl_xor_sync(0xffffffffu, ss, 2);
                if (tg == 0)
                    red[(wm * 32 + mt * 16 + h * 8 + gid) * 2 + wn] = ss;
            }
        __syncthreads();
#pragma unroll
        for (int mt = 0; mt < 2; mt++)
#pragma unroll
            for (int h = 0; h < 2; h++) {
                int rl  = wm * 32 + mt * 16 + h * 8 + gid;
                int row = rb + rl;
                float inv = 1.f / sqrtf(red[rl * 2] + red[rl * 2 + 1]);
                if (row < n) {
#pragma unroll
                    for (int nt = 0; nt < 8; nt++) {
                        int col = wn * 64 + nt * 8 + tg * 2;
                        float2 v = make_float2(acc[mt][nt][2 * h] * inv,
                                               acc[mt][nt][2 * h + 1] * inv);
                        *(float2*)(out + (size_t)row * DDIM + col) = v;
                    }
                }
            }
    }
}

// ---------------------------------------------------------------------------
// Edge scatter: one warp per edge, float4 lanes, vector reduce-add (L2-resident)
// ---------------------------------------------------------------------------
__global__ void scatter_kernel(const int* __restrict__ src,
                               const int* __restrict__ dst,
                               const float* __restrict__ vals, int e) {
    int g = blockIdx.x * blockDim.x + threadIdx.x;
    int edge = g >> 5;
    int lane = g & 31;
    if (edge >= e) return;
    int s = __ldg(src + edge);
    int d = __ldg(dst + edge);
    float v = __ldg(vals + edge);
    float4 m = ((const float4*)(g_support + (size_t)s * DDIM))[lane];
    m.x *= v; m.y *= v; m.z *= v; m.w *= v;
    float* a = g_agg + (size_t)d * DDIM + lane * 4;
    asm volatile("red.global.add.v4.f32 [%0], {%1, %2, %3, %4};"
                 :: "l"(a), "f"(m.x), "f"(m.y), "f"(m.z), "f"(m.w)
                 : "memory");
}

// ---------------------------------------------------------------------------
extern "C" void kernel_launch(void* const* d_in, const int* in_sizes, int n_in,
                              void* d_out, int out_size) {
    const float* x    = (const float*)d_in[0];
    const float* vals = (const float*)d_in[1];
    const float* W_gc = (const float*)d_in[2];
    const float* b_gc = (const float*)d_in[3];
    const float* W2   = (const float*)d_in[4];
    const float* b2   = (const float*)d_in[5];
    const int*   src  = (const int*)d_in[6];
    const int*   dst  = (const int*)d_in[7];

    const int n = in_sizes[0] / DDIM;
    const int e = in_sizes[1];

    float *support, *agg;
    cudaGetSymbolAddress((void**)&support, g_support);
    cudaGetSymbolAddress((void**)&agg, g_agg);

    const int smem = 4 * 128 * ASTR * 4;   // 73728 B
    cudaFuncSetAttribute(hgemm_kernel<0>,
                         cudaFuncAttributeMaxDynamicSharedMemorySize, smem);
    cudaFuncSetAttribute(hgemm_kernel<1>,
                         cudaFuncAttributeMaxDynamicSharedMemorySize, smem);

    int total4 = n * (DDIM / 4);
    zero_agg_kernel<<<(total4 + 255) / 256, 256>>>(total4);

    int gblocks = (n + 127) / 128;
    hgemm_kernel<0><<<gblocks, 256, smem>>>(x, W_gc, b_gc, support, n);

    long long sthreads = (long long)e * 32;
    scatter_kernel<<<(int)((sthreads + 255) / 256), 256>>>(src, dst, vals, e);

    hgemm_kernel<1><<<gblocks, 256, smem>>>(agg, W2, b2, (float*)d_out, n);
}

// round 4
// speedup vs baseline: 2.2991x; 1.3816x over previous
#include <cuda_runtime.h>
#include <cuda_bf16.h>
#include <math.h>

#define DDIM 128
#define NMAX 50000
#define EMAX 800000
#define ASTR 36            // bf16x2 stride per row (32 data + 4 pad) -> conflict-free frags
#define KC   64            // k-chunk (32 bf16x2)
#define CAP  64            // ELL capacity per node (Poisson(16): max deg ~45)

// Scratch (alloc-free rule: __device__ globals)
__device__ float g_support[(size_t)NMAX * DDIM];
__device__ float g_agg[(size_t)NMAX * DDIM];
__device__ int   g_deg[NMAX];
__device__ uint2 g_ell[(size_t)NMAX * CAP];   // (src, val_bits) per slot

// ---------------------------------------------------------------------------
// Zero agg (float4) + deg counters in one kernel
// ---------------------------------------------------------------------------
__global__ void zero_kernel(int total4, int n) {
    int i = blockIdx.x * blockDim.x + threadIdx.x;
    if (i < total4) ((float4*)g_agg)[i] = make_float4(0.f, 0.f, 0.f, 0.f);
    if (i < n) g_deg[i] = 0;
}

// ---------------------------------------------------------------------------
// bf16 split helpers + mma
// ---------------------------------------------------------------------------
__device__ __forceinline__ void split_pair(float x, float y, unsigned& hp, unsigned& lp) {
    __nv_bfloat16 hx = __float2bfloat16_rn(x);
    __nv_bfloat16 hy = __float2bfloat16_rn(y);
    __nv_bfloat16 lx = __float2bfloat16_rn(x - __bfloat162float(hx));
    __nv_bfloat16 ly = __float2bfloat16_rn(y - __bfloat162float(hy));
    hp = (unsigned)__bfloat16_as_ushort(hx) | ((unsigned)__bfloat16_as_ushort(hy) << 16);
    lp = (unsigned)__bfloat16_as_ushort(lx) | ((unsigned)__bfloat16_as_ushort(ly) << 16);
}

__device__ __forceinline__ void mma_bf16(float c[4], const unsigned a[4],
                                         unsigned b0, unsigned b1) {
    asm volatile(
        "mma.sync.aligned.m16n8k16.row.col.f32.bf16.bf16.f32 "
        "{%0,%1,%2,%3}, {%4,%5,%6,%7}, {%8,%9}, {%0,%1,%2,%3};"
        : "+f"(c[0]), "+f"(c[1]), "+f"(c[2]), "+f"(c[3])
        : "r"(a[0]), "r"(a[1]), "r"(a[2]), "r"(a[3]), "r"(b0), "r"(b1));
}

// ---------------------------------------------------------------------------
// bf16 3-split tensor-core GEMM (identical to round-3 version)
// ---------------------------------------------------------------------------
template <int MODE>
__global__ void __launch_bounds__(256, 2)
hgemm_kernel(const float* __restrict__ X,
             const float* __restrict__ W,
             const float* __restrict__ bias,
             float* __restrict__ out, int n) {
    extern __shared__ unsigned smu[];
    unsigned* Ah = smu;                  // [128][36] bf16x2
    unsigned* Al = smu + 128 * ASTR;
    unsigned* Bh = smu + 2 * 128 * ASTR;
    unsigned* Bl = smu + 3 * 128 * ASTR;

    const int tid  = threadIdx.x;
    const int lane = tid & 31;
    const int wid  = tid >> 5;
    const int gid  = lane >> 2;
    const int tg   = lane & 3;
    const int wm   = wid >> 1;
    const int wn   = wid & 1;
    const int rb   = blockIdx.x * 128;

    float acc[2][8][4];
#pragma unroll
    for (int mt = 0; mt < 2; mt++)
#pragma unroll
        for (int nt = 0; nt < 8; nt++)
#pragma unroll
            for (int j = 0; j < 4; j++) acc[mt][nt][j] = 0.f;

#pragma unroll
    for (int kc0 = 0; kc0 < DDIM; kc0 += KC) {
        {
            int rl = tid >> 4;
            int c4 = (tid & 15) * 4;
#pragma unroll
            for (int i = 0; i < 8; i++) {
                int row  = rl + 16 * i;
                int grow = rb + row;
                float4 v = make_float4(0.f, 0.f, 0.f, 0.f);
                if (grow < n)
                    v = *(const float4*)(X + (size_t)grow * DDIM + kc0 + c4);
                if (MODE == 1) {
                    v.x = fmaxf(v.x, 0.f); v.y = fmaxf(v.y, 0.f);
                    v.z = fmaxf(v.z, 0.f); v.w = fmaxf(v.w, 0.f);
                }
                unsigned h0, l0, h1, l1;
                split_pair(v.x, v.y, h0, l0);
                split_pair(v.z, v.w, h1, l1);
                int sa = row * ASTR + (c4 >> 1);
                *(uint2*)(Ah + sa) = make_uint2(h0, h1);
                *(uint2*)(Al + sa) = make_uint2(l0, l1);
            }
        }
        if (MODE == 1) {
            int rl = tid >> 4;
            int c4 = (tid & 15) * 4;
#pragma unroll
            for (int i = 0; i < 8; i++) {
                int nr = rl + 16 * i;
                float4 v = *(const float4*)(W + (size_t)nr * DDIM + kc0 + c4);
                unsigned h0, l0, h1, l1;
                split_pair(v.x, v.y, h0, l0);
                split_pair(v.z, v.w, h1, l1);
                int sa = nr * ASTR + (c4 >> 1);
                *(uint2*)(Bh + sa) = make_uint2(h0, h1);
                *(uint2*)(Bl + sa) = make_uint2(l0, l1);
            }
        } else {
            int nn0 = tid & 31;
            int kh  = tid >> 5;
#pragma unroll
            for (int ik = 0; ik < 4; ik++) {
                int k2l = kh + 8 * ik;
                int gk  = kc0 + 2 * k2l;
#pragma unroll
                for (int jn = 0; jn < 4; jn++) {
                    int nn = nn0 + 32 * jn;
                    float w0 = __ldg(W + (size_t)gk * DDIM + nn);
                    float w1 = __ldg(W + (size_t)(gk + 1) * DDIM + nn);
                    unsigned hp, lp;
                    split_pair(w0, w1, hp, lp);
                    Bh[nn * ASTR + k2l] = hp;
                    Bl[nn * ASTR + k2l] = lp;
                }
            }
        }
        __syncthreads();

#pragma unroll
        for (int ks = 0; ks < 4; ks++) {
            int kb = ks * 8;
            unsigned ah[2][4], al[2][4];
#pragma unroll
            for (int mt = 0; mt < 2; mt++) {
                int base = (wm * 32 + mt * 16 + gid) * ASTR + kb + tg;
                ah[mt][0] = Ah[base];
                ah[mt][1] = Ah[base + 8 * ASTR];
                ah[mt][2] = Ah[base + 4];
                ah[mt][3] = Ah[base + 8 * ASTR + 4];
                al[mt][0] = Al[base];
                al[mt][1] = Al[base + 8 * ASTR];
                al[mt][2] = Al[base + 4];
                al[mt][3] = Al[base + 8 * ASTR + 4];
            }
#pragma unroll
            for (int nt = 0; nt < 8; nt++) {
                int nb = (wn * 64 + nt * 8 + gid) * ASTR + kb + tg;
                unsigned bh0 = Bh[nb], bh1 = Bh[nb + 4];
                unsigned bl0 = Bl[nb], bl1 = Bl[nb + 4];
#pragma unroll
                for (int mt = 0; mt < 2; mt++) {
                    mma_bf16(acc[mt][nt], ah[mt], bh0, bh1);
                    mma_bf16(acc[mt][nt], ah[mt], bl0, bl1);
                    mma_bf16(acc[mt][nt], al[mt], bh0, bh1);
                }
            }
        }
        __syncthreads();
    }

    if (MODE == 0) {
#pragma unroll
        for (int mt = 0; mt < 2; mt++)
#pragma unroll
            for (int h = 0; h < 2; h++) {
                int row = rb + wm * 32 + mt * 16 + h * 8 + gid;
                if (row < n) {
#pragma unroll
                    for (int nt = 0; nt < 8; nt++) {
                        int col = wn * 64 + nt * 8 + tg * 2;
                        float b0 = __ldg(bias + col), b1 = __ldg(bias + col + 1);
                        float2 v = make_float2(acc[mt][nt][2 * h] + b0,
                                               acc[mt][nt][2 * h + 1] + b1);
                        *(float2*)(out + (size_t)row * DDIM + col) = v;
                    }
                }
            }
    } else {
        float* red = (float*)smu;
#pragma unroll
        for (int mt = 0; mt < 2; mt++)
#pragma unroll
            for (int nt = 0; nt < 8; nt++) {
                int col = wn * 64 + nt * 8 + tg * 2;
                float b0 = __ldg(bias + col), b1 = __ldg(bias + col + 1);
                acc[mt][nt][0] += b0; acc[mt][nt][1] += b1;
                acc[mt][nt][2] += b0; acc[mt][nt][3] += b1;
            }
#pragma unroll
        for (int mt = 0; mt < 2; mt++)
#pragma unroll
            for (int h = 0; h < 2; h++) {
                float ss = 0.f;
#pragma unroll
                for (int nt = 0; nt < 8; nt++) {
                    ss = fmaf(acc[mt][nt][2 * h], acc[mt][nt][2 * h], ss);
                    ss = fmaf(acc[mt][nt][2 * h + 1], acc[mt][nt][2 * h + 1], ss);
                }
                ss += __shfl_xor_sync(0xffffffffu, ss, 1);
                ss += __shfl_xor_sync(0xffffffffu, ss, 2);
                if (tg == 0)
                    red[(wm * 32 + mt * 16 + h * 8 + gid) * 2 + wn] = ss;
            }
        __syncthreads();
#pragma unroll
        for (int mt = 0; mt < 2; mt++)
#pragma unroll
            for (int h = 0; h < 2; h++) {
                int rl  = wm * 32 + mt * 16 + h * 8 + gid;
                int row = rb + rl;
                float inv = 1.f / sqrtf(red[rl * 2] + red[rl * 2 + 1]);
                if (row < n) {
#pragma unroll
                    for (int nt = 0; nt < 8; nt++) {
                        int col = wn * 64 + nt * 8 + tg * 2;
                        float2 v = make_float2(acc[mt][nt][2 * h] * inv,
                                               acc[mt][nt][2 * h + 1] * inv);
                        *(float2*)(out + (size_t)row * DDIM + col) = v;
                    }
                }
            }
    }
}

// ---------------------------------------------------------------------------
// Fill ELL: one thread per edge. slot via scalar atomicAdd on deg[dst]
// (800K atomics vs 25.6M before). Overflow (deg > CAP, ~never) falls back to
// a direct scatter-add of the scaled support row.
// ---------------------------------------------------------------------------
__global__ void fill_kernel(const int* __restrict__ src,
                            const int* __restrict__ dst,
                            const float* __restrict__ vals, int e) {
    int i = blockIdx.x * blockDim.x + threadIdx.x;
    if (i >= e) return;
    int d = __ldg(dst + i);
    int s = __ldg(src + i);
    float v = __ldg(vals + i);
    int slot = atomicAdd(&g_deg[d], 1);
    if (slot < CAP) {
        g_ell[(size_t)d * CAP + slot] = make_uint2((unsigned)s, __float_as_uint(v));
    } else {
        const float* srow = g_support + (size_t)s * DDIM;
        float* arow = g_agg + (size_t)d * DDIM;
        for (int c = 0; c < DDIM; c += 4) {
            float4 m = *(const float4*)(srow + c);
            asm volatile("red.global.add.v4.f32 [%0], {%1, %2, %3, %4};"
                         :: "l"(arow + c), "f"(m.x * v), "f"(m.y * v),
                            "f"(m.z * v), "f"(m.w * v) : "memory");
        }
    }
}

// ---------------------------------------------------------------------------
// Gather: one warp per destination node. Register accumulation (float4/lane),
// software-pipelined edge metadata, one red.v4 per node (combines with the
// ~never-taken overflow fallback contributions in zeroed agg).
// ---------------------------------------------------------------------------
__global__ void __launch_bounds__(256)
gather_kernel(int n) {
    int g = blockIdx.x * blockDim.x + threadIdx.x;
    int node = g >> 5;
    int lane = g & 31;
    if (node >= n) return;

    int cnt = min(__ldg(&g_deg[node]), CAP);
    const uint2* el = g_ell + (size_t)node * CAP;

    float4 acc = make_float4(0.f, 0.f, 0.f, 0.f);

    int i = 0;
    if (cnt > 0) {
        uint2 m0 = __ldg(el);                       // prefetch
        for (; i + 1 < cnt; i++) {
            uint2 m1 = __ldg(el + i + 1);           // overlap next meta load
            float v = __uint_as_float(m0.y);
            float4 s = ((const float4*)(g_support + (size_t)m0.x * DDIM))[lane];
            acc.x = fmaf(s.x, v, acc.x);
            acc.y = fmaf(s.y, v, acc.y);
            acc.z = fmaf(s.z, v, acc.z);
            acc.w = fmaf(s.w, v, acc.w);
            m0 = m1;
        }
        float v = __uint_as_float(m0.y);
        float4 s = ((const float4*)(g_support + (size_t)m0.x * DDIM))[lane];
        acc.x = fmaf(s.x, v, acc.x);
        acc.y = fmaf(s.y, v, acc.y);
        acc.z = fmaf(s.z, v, acc.z);
        acc.w = fmaf(s.w, v, acc.w);
    }

    float* a = g_agg + (size_t)node * DDIM + lane * 4;
    asm volatile("red.global.add.v4.f32 [%0], {%1, %2, %3, %4};"
                 :: "l"(a), "f"(acc.x), "f"(acc.y), "f"(acc.z), "f"(acc.w)
                 : "memory");
}

// ---------------------------------------------------------------------------
extern "C" void kernel_launch(void* const* d_in, const int* in_sizes, int n_in,
                              void* d_out, int out_size) {
    const float* x    = (const float*)d_in[0];
    const float* vals = (const float*)d_in[1];
    const float* W_gc = (const float*)d_in[2];
    const float* b_gc = (const float*)d_in[3];
    const float* W2   = (const float*)d_in[4];
    const float* b2   = (const float*)d_in[5];
    const int*   src  = (const int*)d_in[6];
    const int*   dst  = (const int*)d_in[7];

    const int n = in_sizes[0] / DDIM;
    const int e = in_sizes[1];

    float *support, *agg;
    cudaGetSymbolAddress((void**)&support, g_support);
    cudaGetSymbolAddress((void**)&agg, g_agg);

    const int smem = 4 * 128 * ASTR * 4;   // 73728 B
    cudaFuncSetAttribute(hgemm_kernel<0>,
                         cudaFuncAttributeMaxDynamicSharedMemorySize, smem);
    cudaFuncSetAttribute(hgemm_kernel<1>,
                         cudaFuncAttributeMaxDynamicSharedMemorySize, smem);

    // 1) zero agg + deg
    int total4 = n * (DDIM / 4);
    zero_kernel<<<(total4 + 255) / 256, 256>>>(total4, n);

    // 2) support = x @ W_gc + b_gc
    int gblocks = (n + 127) / 128;
    hgemm_kernel<0><<<gblocks, 256, smem>>>(x, W_gc, b_gc, support, n);

    // 3) build ELL by destination (scalar atomics only)
    fill_kernel<<<(e + 255) / 256, 256>>>(src, dst, vals, e);

    // 4) gather per node (register accumulation, coalesced L2 reads)
    long long gthreads = (long long)n * 32;
    gather_kernel<<<(int)((gthreads + 255) / 256), 256>>>(n);

    // 5) out = rownorm(relu(agg) @ W2^T + b2)
    hgemm_kernel<1><<<gblocks, 256, smem>>>(agg, W2, b2, (float*)d_out, n);
}

// round 5
// speedup vs baseline: 2.4008x; 1.0443x over previous
#include <cuda_runtime.h>
#include <cuda_bf16.h>
#include <math.h>

#define DDIM 128
#define NMAX 50000
#define EMAX 800000
#define ASTR 36            // bf16x2 stride per row (32 data + 4 pad) -> conflict-free frags
#define KC   64            // k-chunk (32 bf16x2)
#define CAP  64            // ELL capacity per node (Poisson(16): max deg ~45)
#define OVFMAX 65536

// Scratch (alloc-free rule: __device__ globals)
__device__ float g_support[(size_t)NMAX * DDIM];
__device__ float g_agg[(size_t)NMAX * DDIM];
__device__ int   g_deg[NMAX];
__device__ uint2 g_ell[(size_t)NMAX * CAP];   // (src, val_bits) per slot
__device__ int   g_ovf_cnt;
__device__ uint4 g_ovf[OVFMAX];               // (src, dst, val_bits, -)

// ---------------------------------------------------------------------------
// Zero deg counters + overflow counter (agg is NOT zeroed: gather plain-stores)
// ---------------------------------------------------------------------------
__global__ void zero_kernel(int n) {
    int i = blockIdx.x * blockDim.x + threadIdx.x;
    if (i < n) g_deg[i] = 0;
    if (i == 0) g_ovf_cnt = 0;
}

// ---------------------------------------------------------------------------
// bf16 split helpers + mma
// ---------------------------------------------------------------------------
__device__ __forceinline__ void split_pair(float x, float y, unsigned& hp, unsigned& lp) {
    __nv_bfloat16 hx = __float2bfloat16_rn(x);
    __nv_bfloat16 hy = __float2bfloat16_rn(y);
    __nv_bfloat16 lx = __float2bfloat16_rn(x - __bfloat162float(hx));
    __nv_bfloat16 ly = __float2bfloat16_rn(y - __bfloat162float(hy));
    hp = (unsigned)__bfloat16_as_ushort(hx) | ((unsigned)__bfloat16_as_ushort(hy) << 16);
    lp = (unsigned)__bfloat16_as_ushort(lx) | ((unsigned)__bfloat16_as_ushort(ly) << 16);
}

__device__ __forceinline__ void mma_bf16(float c[4], const unsigned a[4],
                                         unsigned b0, unsigned b1) {
    asm volatile(
        "mma.sync.aligned.m16n8k16.row.col.f32.bf16.bf16.f32 "
        "{%0,%1,%2,%3}, {%4,%5,%6,%7}, {%8,%9}, {%0,%1,%2,%3};"
        : "+f"(c[0]), "+f"(c[1]), "+f"(c[2]), "+f"(c[3])
        : "r"(a[0]), "r"(a[1]), "r"(a[2]), "r"(a[3]), "r"(b0), "r"(b1));
}

// ---------------------------------------------------------------------------
// bf16 3-split tensor-core GEMM (unchanged from round 3/4)
// ---------------------------------------------------------------------------
template <int MODE>
__global__ void __launch_bounds__(256, 2)
hgemm_kernel(const float* __restrict__ X,
             const float* __restrict__ W,
             const float* __restrict__ bias,
             float* __restrict__ out, int n) {
    extern __shared__ unsigned smu[];
    unsigned* Ah = smu;                  // [128][36] bf16x2
    unsigned* Al = smu + 128 * ASTR;
    unsigned* Bh = smu + 2 * 128 * ASTR;
    unsigned* Bl = smu + 3 * 128 * ASTR;

    const int tid  = threadIdx.x;
    const int lane = tid & 31;
    const int wid  = tid >> 5;
    const int gid  = lane >> 2;
    const int tg   = lane & 3;
    const int wm   = wid >> 1;
    const int wn   = wid & 1;
    const int rb   = blockIdx.x * 128;

    float acc[2][8][4];
#pragma unroll
    for (int mt = 0; mt < 2; mt++)
#pragma unroll
        for (int nt = 0; nt < 8; nt++)
#pragma unroll
            for (int j = 0; j < 4; j++) acc[mt][nt][j] = 0.f;

#pragma unroll
    for (int kc0 = 0; kc0 < DDIM; kc0 += KC) {
        {
            int rl = tid >> 4;
            int c4 = (tid & 15) * 4;
#pragma unroll
            for (int i = 0; i < 8; i++) {
                int row  = rl + 16 * i;
                int grow = rb + row;
                float4 v = make_float4(0.f, 0.f, 0.f, 0.f);
                if (grow < n)
                    v = *(const float4*)(X + (size_t)grow * DDIM + kc0 + c4);
                if (MODE == 1) {
                    v.x = fmaxf(v.x, 0.f); v.y = fmaxf(v.y, 0.f);
                    v.z = fmaxf(v.z, 0.f); v.w = fmaxf(v.w, 0.f);
                }
                unsigned h0, l0, h1, l1;
                split_pair(v.x, v.y, h0, l0);
                split_pair(v.z, v.w, h1, l1);
                int sa = row * ASTR + (c4 >> 1);
                *(uint2*)(Ah + sa) = make_uint2(h0, h1);
                *(uint2*)(Al + sa) = make_uint2(l0, l1);
            }
        }
        if (MODE == 1) {
            int rl = tid >> 4;
            int c4 = (tid & 15) * 4;
#pragma unroll
            for (int i = 0; i < 8; i++) {
                int nr = rl + 16 * i;
                float4 v = *(const float4*)(W + (size_t)nr * DDIM + kc0 + c4);
                unsigned h0, l0, h1, l1;
                split_pair(v.x, v.y, h0, l0);
                split_pair(v.z, v.w, h1, l1);
                int sa = nr * ASTR + (c4 >> 1);
                *(uint2*)(Bh + sa) = make_uint2(h0, h1);
                *(uint2*)(Bl + sa) = make_uint2(l0, l1);
            }
        } else {
            int nn0 = tid & 31;
            int kh  = tid >> 5;
#pragma unroll
            for (int ik = 0; ik < 4; ik++) {
                int k2l = kh + 8 * ik;
                int gk  = kc0 + 2 * k2l;
#pragma unroll
                for (int jn = 0; jn < 4; jn++) {
                    int nn = nn0 + 32 * jn;
                    float w0 = __ldg(W + (size_t)gk * DDIM + nn);
                    float w1 = __ldg(W + (size_t)(gk + 1) * DDIM + nn);
                    unsigned hp, lp;
                    split_pair(w0, w1, hp, lp);
                    Bh[nn * ASTR + k2l] = hp;
                    Bl[nn * ASTR + k2l] = lp;
                }
            }
        }
        __syncthreads();

#pragma unroll
        for (int ks = 0; ks < 4; ks++) {
            int kb = ks * 8;
            unsigned ah[2][4], al[2][4];
#pragma unroll
            for (int mt = 0; mt < 2; mt++) {
                int base = (wm * 32 + mt * 16 + gid) * ASTR + kb + tg;
                ah[mt][0] = Ah[base];
                ah[mt][1] = Ah[base + 8 * ASTR];
                ah[mt][2] = Ah[base + 4];
                ah[mt][3] = Ah[base + 8 * ASTR + 4];
                al[mt][0] = Al[base];
                al[mt][1] = Al[base + 8 * ASTR];
                al[mt][2] = Al[base + 4];
                al[mt][3] = Al[base + 8 * ASTR + 4];
            }
#pragma unroll
            for (int nt = 0; nt < 8; nt++) {
                int nb = (wn * 64 + nt * 8 + gid) * ASTR + kb + tg;
                unsigned bh0 = Bh[nb], bh1 = Bh[nb + 4];
                unsigned bl0 = Bl[nb], bl1 = Bl[nb + 4];
#pragma unroll
                for (int mt = 0; mt < 2; mt++) {
                    mma_bf16(acc[mt][nt], ah[mt], bh0, bh1);
                    mma_bf16(acc[mt][nt], ah[mt], bl0, bl1);
                    mma_bf16(acc[mt][nt], al[mt], bh0, bh1);
                }
            }
        }
        __syncthreads();
    }

    if (MODE == 0) {
#pragma unroll
        for (int mt = 0; mt < 2; mt++)
#pragma unroll
            for (int h = 0; h < 2; h++) {
                int row = rb + wm * 32 + mt * 16 + h * 8 + gid;
                if (row < n) {
#pragma unroll
                    for (int nt = 0; nt < 8; nt++) {
                        int col = wn * 64 + nt * 8 + tg * 2;
                        float b0 = __ldg(bias + col), b1 = __ldg(bias + col + 1);
                        float2 v = make_float2(acc[mt][nt][2 * h] + b0,
                                               acc[mt][nt][2 * h + 1] + b1);
                        *(float2*)(out + (size_t)row * DDIM + col) = v;
                    }
                }
            }
    } else {
        float* red = (float*)smu;
#pragma unroll
        for (int mt = 0; mt < 2; mt++)
#pragma unroll
            for (int nt = 0; nt < 8; nt++) {
                int col = wn * 64 + nt * 8 + tg * 2;
                float b0 = __ldg(bias + col), b1 = __ldg(bias + col + 1);
                acc[mt][nt][0] += b0; acc[mt][nt][1] += b1;
                acc[mt][nt][2] += b0; acc[mt][nt][3] += b1;
            }
#pragma unroll
        for (int mt = 0; mt < 2; mt++)
#pragma unroll
            for (int h = 0; h < 2; h++) {
                float ss = 0.f;
#pragma unroll
                for (int nt = 0; nt < 8; nt++) {
                    ss = fmaf(acc[mt][nt][2 * h], acc[mt][nt][2 * h], ss);
                    ss = fmaf(acc[mt][nt][2 * h + 1], acc[mt][nt][2 * h + 1], ss);
                }
                ss += __shfl_xor_sync(0xffffffffu, ss, 1);
                ss += __shfl_xor_sync(0xffffffffu, ss, 2);
                if (tg == 0)
                    red[(wm * 32 + mt * 16 + h * 8 + gid) * 2 + wn] = ss;
            }
        __syncthreads();
#pragma unroll
        for (int mt = 0; mt < 2; mt++)
#pragma unroll
            for (int h = 0; h < 2; h++) {
                int rl  = wm * 32 + mt * 16 + h * 8 + gid;
                int row = rb + rl;
                float inv = 1.f / sqrtf(red[rl * 2] + red[rl * 2 + 1]);
                if (row < n) {
#pragma unroll
                    for (int nt = 0; nt < 8; nt++) {
                        int col = wn * 64 + nt * 8 + tg * 2;
                        float2 v = make_float2(acc[mt][nt][2 * h] * inv,
                                               acc[mt][nt][2 * h + 1] * inv);
                        *(float2*)(out + (size_t)row * DDIM + col) = v;
                    }
                }
            }
    }
}

// ---------------------------------------------------------------------------
// Fill ELL by destination. 800K scalar atomics; overflow edges (deg > CAP,
// ~never) appended to a global list processed after gather.
// ---------------------------------------------------------------------------
__global__ void fill_kernel(const int* __restrict__ src,
                            const int* __restrict__ dst,
                            const float* __restrict__ vals, int e) {
    int i = blockIdx.x * blockDim.x + threadIdx.x;
    if (i >= e) return;
    int d = __ldg(dst + i);
    int s = __ldg(src + i);
    float v = __ldg(vals + i);
    int slot = atomicAdd(&g_deg[d], 1);
    if (slot < CAP) {
        g_ell[(size_t)d * CAP + slot] = make_uint2((unsigned)s, __float_as_uint(v));
    } else {
        int o = atomicAdd(&g_ovf_cnt, 1);
        if (o < OVFMAX)
            g_ovf[o] = make_uint4((unsigned)s, (unsigned)d, __float_as_uint(v), 0u);
    }
}

// ---------------------------------------------------------------------------
// Gather: one warp per destination node, 2 edges per iteration (uint4 meta,
// one-ahead prefetch) for MLP, plain STG.128 result (agg needs no zeroing).
// ---------------------------------------------------------------------------
__global__ void __launch_bounds__(256)
gather_kernel(int n) {
    int g = blockIdx.x * blockDim.x + threadIdx.x;
    int node = g >> 5;
    int lane = g & 31;
    if (node >= n) return;

    int raw = __ldg(&g_deg[node]);
    int cnt = min(raw, CAP);
    const uint4* el4 = (const uint4*)(g_ell + (size_t)node * CAP);

    float4 acc = make_float4(0.f, 0.f, 0.f, 0.f);
    int npairs = cnt >> 1;

    if (npairs > 0) {
        uint4 m = __ldg(el4);
        for (int p = 0; p < npairs; p++) {
            uint4 mn = m;
            if (p + 1 < npairs) mn = __ldg(el4 + p + 1);
            float v0 = __uint_as_float(m.y);
            float v1 = __uint_as_float(m.w);
            float4 s0 = ((const float4*)(g_support + (size_t)m.x * DDIM))[lane];
            float4 s1 = ((const float4*)(g_support + (size_t)m.z * DDIM))[lane];
            acc.x = fmaf(s0.x, v0, acc.x);
            acc.y = fmaf(s0.y, v0, acc.y);
            acc.z = fmaf(s0.z, v0, acc.z);
            acc.w = fmaf(s0.w, v0, acc.w);
            acc.x = fmaf(s1.x, v1, acc.x);
            acc.y = fmaf(s1.y, v1, acc.y);
            acc.z = fmaf(s1.z, v1, acc.z);
            acc.w = fmaf(s1.w, v1, acc.w);
            m = mn;
        }
    }
    if (cnt & 1) {
        uint2 m = __ldg(g_ell + (size_t)node * CAP + (cnt - 1));
        float v = __uint_as_float(m.y);
        float4 s = ((const float4*)(g_support + (size_t)m.x * DDIM))[lane];
        acc.x = fmaf(s.x, v, acc.x);
        acc.y = fmaf(s.y, v, acc.y);
        acc.z = fmaf(s.z, v, acc.z);
        acc.w = fmaf(s.w, v, acc.w);
    }

    // plain store initializes agg (overflow contributions added afterwards)
    *(float4*)(g_agg + (size_t)node * DDIM + lane * 4) = acc;
}

// ---------------------------------------------------------------------------
// Overflow pass (runs AFTER gather): red-add scaled support rows for edges
// beyond CAP. Normally g_ovf_cnt == 0 and this exits immediately.
// ---------------------------------------------------------------------------
__global__ void ovf_kernel() {
    int cnt = g_ovf_cnt;
    if (cnt == 0) return;
    if (cnt > OVFMAX) cnt = OVFMAX;
    int gw = (blockIdx.x * blockDim.x + threadIdx.x) >> 5;
    int lane = threadIdx.x & 31;
    int nw = (gridDim.x * blockDim.x) >> 5;
    for (int i = gw; i < cnt; i += nw) {
        uint4 m = g_ovf[i];
        float v = __uint_as_float(m.z);
        float4 s = ((const float4*)(g_support + (size_t)m.x * DDIM))[lane];
        float* a = g_agg + (size_t)m.y * DDIM + lane * 4;
        asm volatile("red.global.add.v4.f32 [%0], {%1, %2, %3, %4};"
                     :: "l"(a), "f"(s.x * v), "f"(s.y * v), "f"(s.z * v), "f"(s.w * v)
                     : "memory");
    }
}

// ---------------------------------------------------------------------------
extern "C" void kernel_launch(void* const* d_in, const int* in_sizes, int n_in,
                              void* d_out, int out_size) {
    const float* x    = (const float*)d_in[0];
    const float* vals = (const float*)d_in[1];
    const float* W_gc = (const float*)d_in[2];
    const float* b_gc = (const float*)d_in[3];
    const float* W2   = (const float*)d_in[4];
    const float* b2   = (const float*)d_in[5];
    const int*   src  = (const int*)d_in[6];
    const int*   dst  = (const int*)d_in[7];

    const int n = in_sizes[0] / DDIM;
    const int e = in_sizes[1];

    float *support, *agg;
    cudaGetSymbolAddress((void**)&support, g_support);
    cudaGetSymbolAddress((void**)&agg, g_agg);

    const int smem = 4 * 128 * ASTR * 4;   // 73728 B
    cudaFuncSetAttribute(hgemm_kernel<0>,
                         cudaFuncAttributeMaxDynamicSharedMemorySize, smem);
    cudaFuncSetAttribute(hgemm_kernel<1>,
                         cudaFuncAttributeMaxDynamicSharedMemorySize, smem);

    // 1) zero deg + ovf counter (agg needs no zeroing)
    zero_kernel<<<(n + 255) / 256, 256>>>(n);

    // 2) build ELL by destination
    fill_kernel<<<(e + 255) / 256, 256>>>(src, dst, vals, e);

    // 3) support = x @ W_gc + b_gc
    int gblocks = (n + 127) / 128;
    hgemm_kernel<0><<<gblocks, 256, smem>>>(x, W_gc, b_gc, support, n);

    // 4) gather per node (plain-store result)
    long long gthreads = (long long)n * 32;
    gather_kernel<<<(int)((gthreads + 255) / 256), 256>>>(n);

    // 5) overflow contributions (normally empty)
    ovf_kernel<<<32, 256>>>();

    // 6) out = rownorm(relu(agg) @ W2^T + b2)
    hgemm_kernel<1><<<gblocks, 256, smem>>>(agg, W2, b2, (float*)d_out, n);
}

// round 7
// speedup vs baseline: 2.7124x; 1.1298x over previous
#include <cuda_runtime.h>
#include <cuda_bf16.h>
#include <math.h>

#define DDIM 128
#define NMAX 50000
#define EMAX 800000
#define ASTR 36            // bf16x2 stride per row (32 data + 4 pad) -> conflict-free frags
#define KC   64            // k-chunk (32 bf16x2)
#define CAP  64            // ELL capacity per node (Poisson(16): max deg ~45)
#define OVFMAX 65536

// Scratch (alloc-free rule: __device__ globals)
__device__ float g_support[(size_t)NMAX * DDIM];
__device__ float g_agg[(size_t)NMAX * DDIM];
__device__ int   g_deg[NMAX];
__device__ uint2 g_ell[(size_t)NMAX * CAP];   // (src, val_bits) per slot
__device__ int   g_ovf_cnt;
__device__ uint4 g_ovf[OVFMAX];               // (src, dst, val_bits, -)
// pre-split weights, bf16x2 hi/lo, layout [n][k2] (k2 = k/2), 64 k2 per row
__device__ unsigned gW0h[DDIM * (DDIM / 2)], gW0l[DDIM * (DDIM / 2)];
__device__ unsigned gW1h[DDIM * (DDIM / 2)], gW1l[DDIM * (DDIM / 2)];

// ---------------------------------------------------------------------------
__device__ __forceinline__ void split_pair(float x, float y, unsigned& hp, unsigned& lp) {
    __nv_bfloat16 hx = __float2bfloat16_rn(x);
    __nv_bfloat16 hy = __float2bfloat16_rn(y);
    __nv_bfloat16 lx = __float2bfloat16_rn(x - __bfloat162float(hx));
    __nv_bfloat16 ly = __float2bfloat16_rn(y - __bfloat162float(hy));
    hp = (unsigned)__bfloat16_as_ushort(hx) | ((unsigned)__bfloat16_as_ushort(hy) << 16);
    lp = (unsigned)__bfloat16_as_ushort(lx) | ((unsigned)__bfloat16_as_ushort(ly) << 16);
}

__device__ __forceinline__ void mma_bf16(float c[4], const unsigned a[4],
                                         unsigned b0, unsigned b1) {
    asm volatile(
        "mma.sync.aligned.m16n8k16.row.col.f32.bf16.bf16.f32 "
        "{%0,%1,%2,%3}, {%4,%5,%6,%7}, {%8,%9}, {%0,%1,%2,%3};"
        : "+f"(c[0]), "+f"(c[1]), "+f"(c[2]), "+f"(c[3])
        : "r"(a[0]), "r"(a[1]), "r"(a[2]), "r"(a[3]), "r"(b0), "r"(b1));
}

// ---------------------------------------------------------------------------
// Init: zero deg + ovf counter, and pre-split both weight matrices into
// bf16x2 hi/lo [n][k2] layout (W_gc gets transposed here, W2 is already [n][k]).
// ---------------------------------------------------------------------------
__global__ void init_kernel(int n, const float* __restrict__ W_gc,
                            const float* __restrict__ W2) {
    int i = blockIdx.x * blockDim.x + threadIdx.x;
    if (i < n) g_deg[i] = 0;
    if (i == 0) g_ovf_cnt = 0;
    if (i < DDIM * (DDIM / 2)) {                 // W_gc: [k][n] -> [n][k2]
        int nn = i & (DDIM - 1), k2 = i >> 7;
        float w0 = __ldg(W_gc + (size_t)(2 * k2) * DDIM + nn);
        float w1 = __ldg(W_gc + (size_t)(2 * k2 + 1) * DDIM + nn);
        unsigned hp, lp;
        split_pair(w0, w1, hp, lp);
        gW0h[nn * (DDIM / 2) + k2] = hp;
        gW0l[nn * (DDIM / 2) + k2] = lp;
    } else if (i < 2 * DDIM * (DDIM / 2)) {      // W2: [n][k] -> [n][k2]
        int j = i - DDIM * (DDIM / 2);
        int nn = j >> 6, k2 = j & 63;
        float w0 = __ldg(W2 + (size_t)nn * DDIM + 2 * k2);
        float w1 = __ldg(W2 + (size_t)nn * DDIM + 2 * k2 + 1);
        unsigned hp, lp;
        split_pair(w0, w1, hp, lp);
        gW1h[nn * (DDIM / 2) + k2] = hp;
        gW1l[nn * (DDIM / 2) + k2] = lp;
    }
}

// ---------------------------------------------------------------------------
// GEMM tile body (device fn). B comes from pre-split gW* globals (uint4 copy).
// MODE 0: out = X @ W_gc + b     MODE 1: out = rownorm(relu(X) @ W2^T + b)
// ---------------------------------------------------------------------------
template <int MODE>
__device__ __forceinline__ void gemm_tile(const float* __restrict__ X,
                                          const float* __restrict__ bias,
                                          float* __restrict__ out,
                                          int n, int tileIdx, unsigned* smu) {
    unsigned* Ah = smu;                  // [128][36] bf16x2
    unsigned* Al = smu + 128 * ASTR;
    unsigned* Bh = smu + 2 * 128 * ASTR;
    unsigned* Bl = smu + 3 * 128 * ASTR;
    const unsigned* GH = (MODE == 0) ? gW0h : gW1h;
    const unsigned* GL = (MODE == 0) ? gW0l : gW1l;

    const int tid  = threadIdx.x;
    const int lane = tid & 31;
    const int wid  = tid >> 5;
    const int gid  = lane >> 2;
    const int tg   = lane & 3;
    const int wm   = wid >> 1;
    const int wn   = wid & 1;
    const int rb   = tileIdx * 128;

    float acc[2][8][4];
#pragma unroll
    for (int mt = 0; mt < 2; mt++)
#pragma unroll
        for (int nt = 0; nt < 8; nt++)
#pragma unroll
            for (int j = 0; j < 4; j++) acc[mt][nt][j] = 0.f;

#pragma unroll
    for (int kc0 = 0; kc0 < DDIM; kc0 += KC) {
        // ---- stage A [128][64], split hi/lo in-kernel ----
        {
            int rl = tid >> 4;
            int c4 = (tid & 15) * 4;
#pragma unroll
            for (int i = 0; i < 8; i++) {
                int row  = rl + 16 * i;
                int grow = rb + row;
                float4 v = make_float4(0.f, 0.f, 0.f, 0.f);
                if (grow < n)
                    v = *(const float4*)(X + (size_t)grow * DDIM + kc0 + c4);
                if (MODE == 1) {
                    v.x = fmaxf(v.x, 0.f); v.y = fmaxf(v.y, 0.f);
                    v.z = fmaxf(v.z, 0.f); v.w = fmaxf(v.w, 0.f);
                }
                unsigned h0, l0, h1, l1;
                split_pair(v.x, v.y, h0, l0);
                split_pair(v.z, v.w, h1, l1);
                int sa = row * ASTR + (c4 >> 1);
                *(uint2*)(Ah + sa) = make_uint2(h0, h1);
                *(uint2*)(Al + sa) = make_uint2(l0, l1);
            }
        }
        // ---- stage B: straight uint4 copies from pre-split weights ----
        {
            int nn   = tid >> 1;
            int half = tid & 1;
            int gb = nn * (DDIM / 2) + (kc0 >> 1) + half * 16;
            int sb = nn * ASTR + half * 16;
#pragma unroll
            for (int j = 0; j < 4; j++) {
                *(uint4*)(Bh + sb + 4 * j) = *(const uint4*)(GH + gb + 4 * j);
                *(uint4*)(Bl + sb + 4 * j) = *(const uint4*)(GL + gb + 4 * j);
            }
        }
        __syncthreads();

#pragma unroll
        for (int ks = 0; ks < 4; ks++) {
            int kb = ks * 8;
            unsigned ah[2][4], al[2][4];
#pragma unroll
            for (int mt = 0; mt < 2; mt++) {
                int base = (wm * 32 + mt * 16 + gid) * ASTR + kb + tg;
                ah[mt][0] = Ah[base];
                ah[mt][1] = Ah[base + 8 * ASTR];
                ah[mt][2] = Ah[base + 4];
                ah[mt][3] = Ah[base + 8 * ASTR + 4];
                al[mt][0] = Al[base];
                al[mt][1] = Al[base + 8 * ASTR];
                al[mt][2] = Al[base + 4];
                al[mt][3] = Al[base + 8 * ASTR + 4];
            }
#pragma unroll
            for (int nt = 0; nt < 8; nt++) {
                int nb = (wn * 64 + nt * 8 + gid) * ASTR + kb + tg;
                unsigned bh0 = Bh[nb], bh1 = Bh[nb + 4];
                unsigned bl0 = Bl[nb], bl1 = Bl[nb + 4];
#pragma unroll
                for (int mt = 0; mt < 2; mt++) {
                    mma_bf16(acc[mt][nt], ah[mt], bh0, bh1);
                    mma_bf16(acc[mt][nt], ah[mt], bl0, bl1);
                    mma_bf16(acc[mt][nt], al[mt], bh0, bh1);
                }
            }
        }
        __syncthreads();
    }

    if (MODE == 0) {
#pragma unroll
        for (int mt = 0; mt < 2; mt++)
#pragma unroll
            for (int h = 0; h < 2; h++) {
                int row = rb + wm * 32 + mt * 16 + h * 8 + gid;
                if (row < n) {
#pragma unroll
                    for (int nt = 0; nt < 8; nt++) {
                        int col = wn * 64 + nt * 8 + tg * 2;
                        float b0 = __ldg(bias + col), b1 = __ldg(bias + col + 1);
                        float2 v = make_float2(acc[mt][nt][2 * h] + b0,
                                               acc[mt][nt][2 * h + 1] + b1);
                        *(float2*)(out + (size_t)row * DDIM + col) = v;
                    }
                }
            }
    } else {
        float* red = (float*)smu;
#pragma unroll
        for (int mt = 0; mt < 2; mt++)
#pragma unroll
            for (int nt = 0; nt < 8; nt++) {
                int col = wn * 64 + nt * 8 + tg * 2;
                float b0 = __ldg(bias + col), b1 = __ldg(bias + col + 1);
                acc[mt][nt][0] += b0; acc[mt][nt][1] += b1;
                acc[mt][nt][2] += b0; acc[mt][nt][3] += b1;
            }
#pragma unroll
        for (int mt = 0; mt < 2; mt++)
#pragma unroll
            for (int h = 0; h < 2; h++) {
                float ss = 0.f;
#pragma unroll
                for (int nt = 0; nt < 8; nt++) {
                    ss = fmaf(acc[mt][nt][2 * h], acc[mt][nt][2 * h], ss);
                    ss = fmaf(acc[mt][nt][2 * h + 1], acc[mt][nt][2 * h + 1], ss);
                }
                ss += __shfl_xor_sync(0xffffffffu, ss, 1);
                ss += __shfl_xor_sync(0xffffffffu, ss, 2);
                if (tg == 0)
                    red[(wm * 32 + mt * 16 + h * 8 + gid) * 2 + wn] = ss;
            }
        __syncthreads();
#pragma unroll
        for (int mt = 0; mt < 2; mt++)
#pragma unroll
            for (int h = 0; h < 2; h++) {
                int rl  = wm * 32 + mt * 16 + h * 8 + gid;
                int row = rb + rl;
                float inv = 1.f / sqrtf(red[rl * 2] + red[rl * 2 + 1]);
                if (row < n) {
#pragma unroll
                    for (int nt = 0; nt < 8; nt++) {
                        int col = wn * 64 + nt * 8 + tg * 2;
                        float2 v = make_float2(acc[mt][nt][2 * h] * inv,
                                               acc[mt][nt][2 * h + 1] * inv);
                        *(float2*)(out + (size_t)row * DDIM + col) = v;
                    }
                }
            }
    }
}

// ---------------------------------------------------------------------------
// Fused kernel: gemm0 tiles and ELL-fill chunks interleaved in one grid
// (modulo-3 mapping: 1 gemm block per 2 fill chunks -> co-scheduled waves).
// ---------------------------------------------------------------------------
__global__ void __launch_bounds__(256, 2)
fused0_kernel(const float* __restrict__ x, const float* __restrict__ b_gc,
              const int* __restrict__ src, const int* __restrict__ dst,
              const float* __restrict__ vals,
              int n, int e, int gblocks, int fillchunks) {
    extern __shared__ unsigned smu[];
    int b  = blockIdx.x;
    int g3 = b / 3, r = b % 3;
    if (r == 0) {
        if (g3 < gblocks)
            gemm_tile<0>(x, b_gc, g_support, n, g3, smu);
        return;
    }
    int fb = g3 * 2 + (r - 1);
    if (fb >= fillchunks) return;
    // fill: 1024 edges per chunk, 4 per thread
    int base = fb * 1024 + threadIdx.x * 4;
#pragma unroll
    for (int j = 0; j < 4; j++) {
        int i = base + j;
        if (i >= e) break;
        int d = __ldg(dst + i);
        int s = __ldg(src + i);
        float v = __ldg(vals + i);
        int slot = atomicAdd(&g_deg[d], 1);
        if (slot < CAP) {
            g_ell[(size_t)d * CAP + slot] = make_uint2((unsigned)s, __float_as_uint(v));
        } else {
            int o = atomicAdd(&g_ovf_cnt, 1);
            if (o < OVFMAX)
                g_ovf[o] = make_uint4((unsigned)s, (unsigned)d, __float_as_uint(v), 0u);
        }
    }
}

__global__ void __launch_bounds__(256, 2)
gemm1_kernel(const float* __restrict__ b2, float* __restrict__ out, int n) {
    extern __shared__ unsigned smu[];
    gemm_tile<1>(g_agg, b2, out, n, blockIdx.x, smu);
}

// ---------------------------------------------------------------------------
// Gather: one warp per node, 4 edges/iter (2x uint4 meta) for MLP, plain
// STG.128 (agg needs no zeroing). Overflow edges (deg>CAP, ~never) are
// resolved in-kernel by scanning the ovf list.
// ---------------------------------------------------------------------------
__global__ void __launch_bounds__(256)
gather_kernel(int n) {
    int g = blockIdx.x * blockDim.x + threadIdx.x;
    int node = g >> 5;
    int lane = g & 31;
    if (node >= n) return;

    int raw = __ldg(&g_deg[node]);
    int cnt = min(raw, CAP);
    const uint4* el4 = (const uint4*)(g_ell + (size_t)node * CAP);

    float4 acc = make_float4(0.f, 0.f, 0.f, 0.f);
    int nq = cnt >> 2;

    for (int q = 0; q < nq; q++) {
        uint4 m0 = __ldg(el4 + 2 * q);
        uint4 m1 = __ldg(el4 + 2 * q + 1);
        float4 s0 = ((const float4*)(g_support + (size_t)m0.x * DDIM))[lane];
        float4 s1 = ((const float4*)(g_support + (size_t)m0.z * DDIM))[lane];
        float4 s2 = ((const float4*)(g_support + (size_t)m1.x * DDIM))[lane];
        float4 s3 = ((const float4*)(g_support + (size_t)m1.z * DDIM))[lane];
        float v0 = __uint_as_float(m0.y), v1 = __uint_as_float(m0.w);
        float v2 = __uint_as_float(m1.y), v3 = __uint_as_float(m1.w);
        acc.x = fmaf(s0.x, v0, acc.x); acc.y = fmaf(s0.y, v0, acc.y);
        acc.z = fmaf(s0.z, v0, acc.z); acc.w = fmaf(s0.w, v0, acc.w);
        acc.x = fmaf(s1.x, v1, acc.x); acc.y = fmaf(s1.y, v1, acc.y);
        acc.z = fmaf(s1.z, v1, acc.z); acc.w = fmaf(s1.w, v1, acc.w);
        acc.x = fmaf(s2.x, v2, acc.x); acc.y = fmaf(s2.y, v2, acc.y);
        acc.z = fmaf(s2.z, v2, acc.z); acc.w = fmaf(s2.w, v2, acc.w);
        acc.x = fmaf(s3.x, v3, acc.x); acc.y = fmaf(s3.y, v3, acc.y);
        acc.z = fmaf(s3.z, v3, acc.z); acc.w = fmaf(s3.w, v3, acc.w);
    }
    for (int i = nq * 4; i < cnt; i++) {
        uint2 m = __ldg(g_ell + (size_t)node * CAP + i);
        float v = __uint_as_float(m.y);
        float4 s = ((const float4*)(g_support + (size_t)m.x * DDIM))[lane];
        acc.x = fmaf(s.x, v, acc.x); acc.y = fmaf(s.y, v, acc.y);
        acc.z = fmaf(s.z, v, acc.z); acc.w = fmaf(s.w, v, acc.w);
    }
    if (raw > CAP) {        // ~never: pick up this node's overflow edges
        int c = min(g_ovf_cnt, OVFMAX);
        for (int i = 0; i < c; i++) {
            uint4 m = g_ovf[i];
            if (m.y == (unsigned)node) {
                float v = __uint_as_float(m.z);
                float4 s = ((const float4*)(g_support + (size_t)m.x * DDIM))[lane];
                acc.x = fmaf(s.x, v, acc.x); acc.y = fmaf(s.y, v, acc.y);
                acc.z = fmaf(s.z, v, acc.z); acc.w = fmaf(s.w, v, acc.w);
            }
        }
    }

    *(float4*)(g_agg + (size_t)node * DDIM + lane * 4) = acc;
}

// ---------------------------------------------------------------------------
extern "C" void kernel_launch(void* const* d_in, const int* in_sizes, int n_in,
                              void* d_out, int out_size) {
    const float* x    = (const float*)d_in[0];
    const float* vals = (const float*)d_in[1];
    const float* W_gc = (const float*)d_in[2];
    const float* b_gc = (const float*)d_in[3];
    const float* W2   = (const float*)d_in[4];
    const float* b2   = (const float*)d_in[5];
    const int*   src  = (const int*)d_in[6];
    const int*   dst  = (const int*)d_in[7];

    const int n = in_sizes[0] / DDIM;
    const int e = in_sizes[1];

    const int smem = 4 * 128 * ASTR * 4;   // 73728 B
    cudaFuncSetAttribute(fused0_kernel,
                         cudaFuncAttributeMaxDynamicSharedMemorySize, smem);
    cudaFuncSetAttribute(gemm1_kernel,
                         cudaFuncAttributeMaxDynamicSharedMemorySize, smem);

    // 1) init: zero deg/ovf + pre-split weights
    int ithreads = n > 2 * DDIM * (DDIM / 2) ? n : 2 * DDIM * (DDIM / 2);
    init_kernel<<<(ithreads + 255) / 256, 256>>>(n, W_gc, W2);

    // 2) fused: gemm0 (support = x@W_gc + b_gc) || ELL fill
    int gblocks = (n + 127) / 128;
    int fillchunks = (e + 1023) / 1024;
    int gb2 = gblocks > (fillchunks + 1) / 2 ? gblocks : (fillchunks + 1) / 2;
    fused0_kernel<<<3 * gb2, 256, smem>>>(x, b_gc, src, dst, vals,
                                          n, e, gblocks, fillchunks);

    // 3) gather per node (handles overflow in-kernel)
    long long gthreads = (long long)n * 32;
    gather_kernel<<<(int)((gthreads + 255) / 256), 256>>>(n);

    // 4) out = rownorm(relu(agg) @ W2^T + b2)
    gemm1_kernel<<<gblocks, 256, smem>>>(b2, (float*)d_out, n);
}